// round 2
// baseline (speedup 1.0000x reference)
#include <cuda_runtime.h>
#include <math.h>

#define BB   4
#define SS   1024
#define DD   2048
#define NH   32
#define NKV  8
#define HDIM 64
#define HALFD 32
#define NREP 4

// Scratch (allocation-free rule: __device__ globals)
__device__ float g_Q[BB * SS * NH * HDIM];    // [b,s,h,d]  33.5 MB
__device__ float g_K[BB * SS * NKV * HDIM];   // [b,s,kh,d]  8.4 MB
__device__ float g_V[BB * SS * NKV * HDIM];   // [b,s,kh,d]  8.4 MB
__device__ float g_AO[BB * SS * DD];          // [b,s,h,d]  33.5 MB

// ---------------------------------------------------------------------------
// SGEMM: C[M,N] = A[M,K] @ W[K,N], row-major. M%128==0, N%128==0, K%32==0.
// 256 threads, 128x128 tile, BK=16, 8x8 micro-tile, double-buffered smem
// with register prefetch (one barrier per k-step).
// ---------------------------------------------------------------------------
__global__ __launch_bounds__(256) void sgemm_kernel(
    const float* __restrict__ A, const float* __restrict__ W,
    float* __restrict__ C, int M, int N, int K)
{
    __shared__ float As[2][16][128];   // [buf][k][m]
    __shared__ float Bs[2][16][128];   // [buf][k][n]

    const int tid = threadIdx.x;
    const int m0  = blockIdx.y * 128;
    const int n0  = blockIdx.x * 128;
    const int tx  = tid & 15;
    const int ty  = tid >> 4;
    const int row0 = ty * 8;
    const int col0 = tx * 8;

    // load-index precompute (2 float4 each for A and B per thread)
    const int ar0 = tid >> 1;                    // 0..127
    const int ac0 = (tid & 1) << 3;              // 0 or 8  (two float4 = 8 floats)
    const int br0 = tid >> 5;                    // 0..7  (+8 for second)
    const int bc0 = (tid & 31) << 2;             // 0..124

    float acc[8][8];
#pragma unroll
    for (int i = 0; i < 8; i++)
#pragma unroll
        for (int j = 0; j < 8; j++) acc[i][j] = 0.f;

    const int nk = K >> 4;

    // --- prologue: stage k-tile 0 into buffer 0 ---
    {
        float4 a0 = *(const float4*)(A + (size_t)(m0 + ar0) * K + ac0);
        float4 a1 = *(const float4*)(A + (size_t)(m0 + ar0) * K + ac0 + 4);
        float4 b0 = *(const float4*)(W + (size_t)(br0)     * N + n0 + bc0);
        float4 b1 = *(const float4*)(W + (size_t)(br0 + 8) * N + n0 + bc0);
        As[0][ac0 + 0][ar0] = a0.x;  As[0][ac0 + 1][ar0] = a0.y;
        As[0][ac0 + 2][ar0] = a0.z;  As[0][ac0 + 3][ar0] = a0.w;
        As[0][ac0 + 4][ar0] = a1.x;  As[0][ac0 + 5][ar0] = a1.y;
        As[0][ac0 + 6][ar0] = a1.z;  As[0][ac0 + 7][ar0] = a1.w;
        *(float4*)&Bs[0][br0][bc0]     = b0;
        *(float4*)&Bs[0][br0 + 8][bc0] = b1;
    }
    __syncthreads();

    int buf = 0;
    for (int kt = 0; kt < nk; kt++) {
        // register prefetch of next k-tile (overlaps with FMA loop below)
        float4 a0, a1, b0, b1;
        const bool has_next = (kt + 1 < nk);
        if (has_next) {
            int k0 = (kt + 1) << 4;
            a0 = *(const float4*)(A + (size_t)(m0 + ar0) * K + k0 + ac0);
            a1 = *(const float4*)(A + (size_t)(m0 + ar0) * K + k0 + ac0 + 4);
            b0 = *(const float4*)(W + (size_t)(k0 + br0)     * N + n0 + bc0);
            b1 = *(const float4*)(W + (size_t)(k0 + br0 + 8) * N + n0 + bc0);
        }

#pragma unroll
        for (int kk = 0; kk < 16; kk++) {
            float a[8], b[8];
            *(float4*)&a[0] = *(const float4*)&As[buf][kk][row0];
            *(float4*)&a[4] = *(const float4*)&As[buf][kk][row0 + 4];
            *(float4*)&b[0] = *(const float4*)&Bs[buf][kk][col0];
            *(float4*)&b[4] = *(const float4*)&Bs[buf][kk][col0 + 4];
#pragma unroll
            for (int i = 0; i < 8; i++)
#pragma unroll
                for (int j = 0; j < 8; j++)
                    acc[i][j] += a[i] * b[j];
        }

        if (has_next) {
            int nb = buf ^ 1;
            As[nb][ac0 + 0][ar0] = a0.x;  As[nb][ac0 + 1][ar0] = a0.y;
            As[nb][ac0 + 2][ar0] = a0.z;  As[nb][ac0 + 3][ar0] = a0.w;
            As[nb][ac0 + 4][ar0] = a1.x;  As[nb][ac0 + 5][ar0] = a1.y;
            As[nb][ac0 + 6][ar0] = a1.z;  As[nb][ac0 + 7][ar0] = a1.w;
            *(float4*)&Bs[nb][br0][bc0]     = b0;
            *(float4*)&Bs[nb][br0 + 8][bc0] = b1;
            __syncthreads();
            buf = nb;
        }
    }

#pragma unroll
    for (int i = 0; i < 8; i++) {
        float* cp = C + (size_t)(m0 + row0 + i) * N + n0 + col0;
        *(float4*)(cp + 0) = make_float4(acc[i][0], acc[i][1], acc[i][2], acc[i][3]);
        *(float4*)(cp + 4) = make_float4(acc[i][4], acc[i][5], acc[i][6], acc[i][7]);
    }
}

// ---------------------------------------------------------------------------
// RoPE, in place. t layout [b,s,heads,64]; pair i -> (t[2i], t[2i+1]).
// cos/sin: [S, 32].
// ---------------------------------------------------------------------------
__global__ void rope_kernel(float* __restrict__ t, const float* __restrict__ cs,
                            const float* __restrict__ sn, int heads, int total_pairs)
{
    int i = blockIdx.x * blockDim.x + threadIdx.x;
    if (i >= total_pairs) return;
    int j = i & (HALFD - 1);                    // pair index within head
    int s = (i / (HALFD * heads)) % SS;         // sequence position
    float2 v = *(float2*)(t + 2 * (size_t)i);
    float c  = cs[s * HALFD + j];
    float sv = sn[s * HALFD + j];
    float2 r;
    r.x = v.x * c - v.y * sv;
    r.y = v.x * sv + v.y * c;
    *(float2*)(t + 2 * (size_t)i) = r;
}

// ---------------------------------------------------------------------------
// Causal flash attention. One block = 64 query rows of one (b,h).
// 256 threads: thread owns query row r = tid/4 and 16-col / 16-dim slice
// (q4 = tid%4). Online softmax state reduced within the 4-lane quad.
// P is written back into the (dead) K smem buffer to stay under 48 KB.
// ---------------------------------------------------------------------------
__global__ __launch_bounds__(256) void attn_kernel(
    const float* __restrict__ Q, const float* __restrict__ Kg,
    const float* __restrict__ Vg, float* __restrict__ O)
{
    __shared__ float Ks[64][68];   // K tile, later reused for P
    __shared__ float Vs[64][68];

    const int tid  = threadIdx.x;
    const int m0   = blockIdx.x * 64;
    const int bh   = blockIdx.y;
    const int b    = bh >> 5;
    const int h    = bh & 31;
    const int kvh  = h >> 2;                 // GQA: 4 q-heads per kv-head
    const int r    = tid >> 2;
    const int q4   = tid & 3;
    const int qpos = m0 + r;

    // Q row into registers, pre-scaled by 1/sqrt(64)
    float q[64];
    {
        const float* qp = Q + (((size_t)(b * SS + qpos)) * NH + h) * HDIM;
#pragma unroll
        for (int d4 = 0; d4 < 16; d4++) {
            float4 v = *(const float4*)(qp + d4 * 4);
            q[4 * d4 + 0] = v.x * 0.125f;
            q[4 * d4 + 1] = v.y * 0.125f;
            q[4 * d4 + 2] = v.z * 0.125f;
            q[4 * d4 + 3] = v.w * 0.125f;
        }
    }

    float oa[16];
#pragma unroll
    for (int i = 0; i < 16; i++) oa[i] = 0.f;
    float mrow = -1e30f, lrow = 0.f;

    const int ntiles = blockIdx.x + 1;       // causal: key tiles 0..m0/64
    for (int jt = 0; jt < ntiles; jt++) {
        const int n0 = jt * 64;
        __syncthreads();                     // prior-iter smem reads complete

        // stage K and V tiles
#pragma unroll
        for (int i = 0; i < 4; i++) {
            int f  = tid + i * 256;          // 0..1023 float4 slots
            int rr = f >> 4;                 // 0..63
            int c4 = (f & 15) << 2;          // 0..60
            size_t src = (((size_t)(b * SS + n0 + rr)) * NKV + kvh) * HDIM + c4;
            *(float4*)&Ks[rr][c4] = *(const float4*)(Kg + src);
            *(float4*)&Vs[rr][c4] = *(const float4*)(Vg + src);
        }
        __syncthreads();

        // scores for this thread's 16 key columns
        float svv[16];
#pragma unroll
        for (int cc = 0; cc < 16; cc++) {
            int c = q4 * 16 + cc;
            const float4* kr = (const float4*)&Ks[c][0];
            float a0 = 0.f, a1 = 0.f, a2 = 0.f, a3 = 0.f;
#pragma unroll
            for (int d4 = 0; d4 < 16; d4++) {
                float4 kv = kr[d4];
                a0 += q[4 * d4 + 0] * kv.x;
                a1 += q[4 * d4 + 1] * kv.y;
                a2 += q[4 * d4 + 2] * kv.z;
                a3 += q[4 * d4 + 3] * kv.w;
            }
            float val = (a0 + a1) + (a2 + a3);
            svv[cc] = (n0 + c <= qpos) ? val : -1e30f;
        }

        // online softmax (quad = same row, lanes differ in bit0/bit1)
        float tmax = svv[0];
#pragma unroll
        for (int cc = 1; cc < 16; cc++) tmax = fmaxf(tmax, svv[cc]);
        tmax = fmaxf(tmax, __shfl_xor_sync(0xffffffffu, tmax, 1));
        tmax = fmaxf(tmax, __shfl_xor_sync(0xffffffffu, tmax, 2));
        float mnew  = fmaxf(mrow, tmax);
        float alpha = __expf(mrow - mnew);
        float ps = 0.f;
#pragma unroll
        for (int cc = 0; cc < 16; cc++) {
            float p = __expf(svv[cc] - mnew);
            svv[cc] = p;
            ps += p;
        }
        ps += __shfl_xor_sync(0xffffffffu, ps, 1);
        ps += __shfl_xor_sync(0xffffffffu, ps, 2);
        lrow = lrow * alpha + ps;
        mrow = mnew;
#pragma unroll
        for (int i = 0; i < 16; i++) oa[i] *= alpha;

        __syncthreads();                     // K reads finished -> reuse as P
#pragma unroll
        for (int cc4 = 0; cc4 < 4; cc4++)
            *(float4*)&Ks[r][q4 * 16 + cc4 * 4] =
                make_float4(svv[cc4 * 4 + 0], svv[cc4 * 4 + 1],
                            svv[cc4 * 4 + 2], svv[cc4 * 4 + 3]);
        __syncthreads();

        // O[r, dims q4*16..+15] += P[r,:] @ V[:, dims]
#pragma unroll
        for (int c4 = 0; c4 < 16; c4++) {
            float4 p4 = *(const float4*)&Ks[r][c4 * 4];
            float pv[4] = {p4.x, p4.y, p4.z, p4.w};
#pragma unroll
            for (int u = 0; u < 4; u++) {
                const float4* vr = (const float4*)&Vs[c4 * 4 + u][q4 * 16];
#pragma unroll
                for (int w = 0; w < 4; w++) {
                    float4 vv = vr[w];
                    oa[w * 4 + 0] += pv[u] * vv.x;
                    oa[w * 4 + 1] += pv[u] * vv.y;
                    oa[w * 4 + 2] += pv[u] * vv.z;
                    oa[w * 4 + 3] += pv[u] * vv.w;
                }
            }
        }
    }

    // normalize and write: g_AO layout [b,s,h,d] == [b,s,D]
    float inv = 1.0f / lrow;
    float* op = O + (((size_t)(b * SS + qpos)) * NH + h) * HDIM + q4 * 16;
#pragma unroll
    for (int w = 0; w < 4; w++) {
        float4 v = make_float4(oa[w * 4 + 0] * inv, oa[w * 4 + 1] * inv,
                               oa[w * 4 + 2] * inv, oa[w * 4 + 3] * inv);
        *(float4*)(op + w * 4) = v;
    }
}

// ---------------------------------------------------------------------------
extern "C" void kernel_launch(void* const* d_in, const int* in_sizes, int n_in,
                              void* d_out, int out_size)
{
    const float* x    = (const float*)d_in[0];
    const float* pcos = (const float*)d_in[1];
    const float* psin = (const float*)d_in[2];
    const float* wq   = (const float*)d_in[3];
    const float* wk   = (const float*)d_in[4];
    const float* wv   = (const float*)d_in[5];
    const float* wo   = (const float*)d_in[6];
    float* out        = (float*)d_out;

    float *Qd, *Kd, *Vd, *AOd;
    cudaGetSymbolAddress((void**)&Qd,  g_Q);
    cudaGetSymbolAddress((void**)&Kd,  g_K);
    cudaGetSymbolAddress((void**)&Vd,  g_V);
    cudaGetSymbolAddress((void**)&AOd, g_AO);

    const int M = BB * SS;                   // 4096

    // QKV projections
    dim3 gq(DD / 128, M / 128);              // (16, 32)
    sgemm_kernel<<<gq, 256>>>(x, wq, Qd, M, DD, DD);
    dim3 gkv((NKV * HDIM) / 128, M / 128);   // (4, 32)
    sgemm_kernel<<<gkv, 256>>>(x, wk, Kd, M, NKV * HDIM, DD);
    sgemm_kernel<<<gkv, 256>>>(x, wv, Vd, M, NKV * HDIM, DD);

    // RoPE on Q and K
    int qpairs = BB * SS * NH * HALFD;       // 4,194,304
    int kpairs = BB * SS * NKV * HALFD;      // 1,048,576
    rope_kernel<<<(qpairs + 255) / 256, 256>>>(Qd, pcos, psin, NH, qpairs);
    rope_kernel<<<(kpairs + 255) / 256, 256>>>(Kd, pcos, psin, NKV, kpairs);

    // causal flash attention
    dim3 ga(SS / 64, BB * NH);               // (16, 128)
    attn_kernel<<<ga, 256>>>(Qd, Kd, Vd, AOd);

    // output projection
    sgemm_kernel<<<gq, 256>>>(AOd, wo, out, M, DD, DD);
}

// round 11
// speedup vs baseline: 1.2573x; 1.2573x over previous
#include <cuda_runtime.h>
#include <cuda_bf16.h>
#include <math.h>
#include <stdint.h>

#define BB   4
#define SS   1024
#define DD   2048
#define NH   32
#define NKV  8
#define HDIM 64
#define HALFD 32
#define KVD  (NKV * HDIM)   // 512

// ---------------- scratch (__device__ globals; no allocs allowed) ----------
__device__ float g_Q [BB * SS * NH  * HDIM];
__device__ float g_K [BB * SS * NKV * HDIM];
__device__ float g_V [BB * SS * NKV * HDIM];
__device__ float g_AO[BB * SS * DD];

__device__ __nv_bfloat16 g_xh [BB * SS * DD];
__device__ __nv_bfloat16 g_xl [BB * SS * DD];
__device__ __nv_bfloat16 g_aoh[BB * SS * DD];
__device__ __nv_bfloat16 g_aol[BB * SS * DD];
// transposed weights [N,K] row-major, split hi/lo
__device__ __nv_bfloat16 g_wqh[DD  * DD];
__device__ __nv_bfloat16 g_wql[DD  * DD];
__device__ __nv_bfloat16 g_wkh[KVD * DD];
__device__ __nv_bfloat16 g_wkl[KVD * DD];
__device__ __nv_bfloat16 g_wvh[KVD * DD];
__device__ __nv_bfloat16 g_wvl[KVD * DD];
__device__ __nv_bfloat16 g_woh[DD  * DD];
__device__ __nv_bfloat16 g_wol[DD  * DD];

// ---------------- helpers (baseline PTX only: sm_80-level features) --------
static __device__ __forceinline__ uint32_t smem_u32(const void* p) {
    uint32_t a;
    asm("{ .reg .u64 t; cvta.to.shared.u64 t, %1; cvt.u32.u64 %0, t; }"
        : "=r"(a) : "l"(p));
    return a;
}
static __device__ __forceinline__ void cp_async16(uint32_t saddr, const void* g) {
    asm volatile("cp.async.cg.shared.global [%0], [%1], 16;"
                 :: "r"(saddr), "l"(g) : "memory");
}
static __device__ __forceinline__ void cp_commit() {
    asm volatile("cp.async.commit_group;" ::: "memory");
}
template <int N>
static __device__ __forceinline__ void cp_wait() {
    asm volatile("cp.async.wait_group %0;" :: "n"(N) : "memory");
}
// D = A(16x16 bf16, row) * B(16x8 bf16, col) + D, fp32 accumulate
static __device__ __forceinline__ void mma_bf16(float* c, const uint32_t* a,
                                                const uint32_t* b) {
    asm volatile(
        "mma.sync.aligned.m16n8k16.row.col.f32.bf16.bf16.f32 "
        "{%0,%1,%2,%3}, {%4,%5,%6,%7}, {%8,%9}, {%0,%1,%2,%3};"
        : "+f"(c[0]), "+f"(c[1]), "+f"(c[2]), "+f"(c[3])
        : "r"(a[0]), "r"(a[1]), "r"(a[2]), "r"(a[3]), "r"(b[0]), "r"(b[1]));
}

// ---------------------------------------------------------------------------
// split: h = bf16(x), l = bf16(x - h).  n % 4 == 0.
// ---------------------------------------------------------------------------
__global__ void split_kernel(const float* __restrict__ x,
                             __nv_bfloat16* __restrict__ h,
                             __nv_bfloat16* __restrict__ l, int n4)
{
    int i = blockIdx.x * blockDim.x + threadIdx.x;
    if (i >= n4) return;
    float4 v = *((const float4*)x + i);
    __nv_bfloat16 h0 = __float2bfloat16(v.x), h1 = __float2bfloat16(v.y);
    __nv_bfloat16 h2 = __float2bfloat16(v.z), h3 = __float2bfloat16(v.w);
    __nv_bfloat162 hh0 = {h0, h1}, hh1 = {h2, h3};
    __nv_bfloat162 ll0 = {__float2bfloat16(v.x - __bfloat162float(h0)),
                          __float2bfloat16(v.y - __bfloat162float(h1))};
    __nv_bfloat162 ll1 = {__float2bfloat16(v.z - __bfloat162float(h2)),
                          __float2bfloat16(v.w - __bfloat162float(h3))};
    ((__nv_bfloat162*)h)[2 * i]     = hh0;
    ((__nv_bfloat162*)h)[2 * i + 1] = hh1;
    ((__nv_bfloat162*)l)[2 * i]     = ll0;
    ((__nv_bfloat162*)l)[2 * i + 1] = ll1;
}

// ---------------------------------------------------------------------------
// transpose + split: W[K,N] fp32 -> Th/Tl[N,K] bf16.  K,N % 32 == 0.
// ---------------------------------------------------------------------------
__global__ void tsplit_kernel(const float* __restrict__ W,
                              __nv_bfloat16* __restrict__ Th,
                              __nv_bfloat16* __restrict__ Tl, int K, int N)
{
    __shared__ float t[32][33];
    int n0 = blockIdx.x * 32, k0 = blockIdx.y * 32;
    int tx = threadIdx.x, ty = threadIdx.y;
#pragma unroll
    for (int i = 0; i < 4; i++)
        t[ty + i * 8][tx] = W[(size_t)(k0 + ty + i * 8) * N + n0 + tx];
    __syncthreads();
#pragma unroll
    for (int i = 0; i < 4; i++) {
        float v = t[tx][ty + i * 8];
        __nv_bfloat16 h = __float2bfloat16(v);
        size_t o = (size_t)(n0 + ty + i * 8) * K + k0 + tx;
        Th[o] = h;
        Tl[o] = __float2bfloat16(v - __bfloat162float(h));
    }
}

// ---------------------------------------------------------------------------
// mma.sync split-bf16 GEMM: C[M,N] = Ahl[M,K] x Bhl[N,K]^T  (fp32)
// 256 thr (8 warps, 2x4), CTA tile 128x128, warp tile 64x32, BK=32.
// smem rows padded to 40 bf16 (80B) -> conflict-free fragment loads.
// cp.async double buffer. dynamic smem = 2 x 40960 = 81920 B.
// ---------------------------------------------------------------------------
#define GSTRIDE  40                       // bf16 per smem row (32 data + 8 pad)
#define ROWB     (GSTRIDE * 2)            // 80 bytes
#define TILE_B   (128 * ROWB)             // 10240
#define OFF_AH   0
#define OFF_AL   TILE_B
#define OFF_BH   (2 * TILE_B)
#define OFF_BL   (3 * TILE_B)
#define BUF_B    (4 * TILE_B)             // 40960
#define GEMM_SMEM (2 * BUF_B)             // 81920

__global__ __launch_bounds__(256, 1) void gemm_mma_kernel(
    const __nv_bfloat16* __restrict__ Ah, const __nv_bfloat16* __restrict__ Al,
    const __nv_bfloat16* __restrict__ Bh, const __nv_bfloat16* __restrict__ Bl,
    float* __restrict__ C, int M, int N, int K)
{
    extern __shared__ char smem[];
    const int tid  = threadIdx.x;
    const int wid  = tid >> 5;
    const int lane = tid & 31;
    const int m0   = blockIdx.y * 128;
    const int n0   = blockIdx.x * 128;
    const int wm   = wid & 1;             // warp row (0..1) -> 64 rows
    const int wn   = wid >> 1;            // warp col (0..3) -> 32 cols
    const uint32_t sbase = smem_u32(smem);

    float acc[4][4][4];
#pragma unroll
    for (int a = 0; a < 4; a++)
#pragma unroll
        for (int b = 0; b < 4; b++)
#pragma unroll
            for (int c = 0; c < 4; c++) acc[a][b][c] = 0.f;

    const int nk = K >> 5;                // chunks of 32

    // stage chunk ck into buffer buf (2 x 16B slots per tile per thread)
    auto stage = [&](int ck, int buf) {
        const int k0 = ck << 5;
        const uint32_t sb = sbase + buf * BUF_B;
#pragma unroll
        for (int j = 0; j < 2; j++) {
            int slot = tid * 2 + j;       // 0..511
            int row  = slot >> 2;         // 0..127
            int k4   = slot & 3;          // 16B segment within 64B of K-data
            uint32_t so = (uint32_t)(row * ROWB + k4 * 16);
            size_t  ga = (size_t)(m0 + row) * K + k0 + k4 * 8;
            size_t  gb = (size_t)(n0 + row) * K + k0 + k4 * 8;
            cp_async16(sb + OFF_AH + so, Ah + ga);
            cp_async16(sb + OFF_AL + so, Al + ga);
            cp_async16(sb + OFF_BH + so, Bh + gb);
            cp_async16(sb + OFF_BL + so, Bl + gb);
        }
    };

    auto compute = [&](int buf) {
        const char* sb = smem + buf * BUF_B;
#pragma unroll
        for (int ks = 0; ks < 2; ks++) {  // two k16 steps in BK=32
            const int ksb = ks * 32;      // byte offset of k-step (16 bf16)
            uint32_t ah[4][4], al[4][4], bh[4][2], bl[4][2];
#pragma unroll
            for (int mi = 0; mi < 4; mi++) {
                uint32_t ro = (uint32_t)((wm * 64 + mi * 16 + (lane >> 2)) * ROWB
                                         + ksb + (lane & 3) * 4);
                ah[mi][0] = *(const uint32_t*)(sb + OFF_AH + ro);
                ah[mi][1] = *(const uint32_t*)(sb + OFF_AH + ro + 8 * ROWB);
                ah[mi][2] = *(const uint32_t*)(sb + OFF_AH + ro + 16);
                ah[mi][3] = *(const uint32_t*)(sb + OFF_AH + ro + 8 * ROWB + 16);
                al[mi][0] = *(const uint32_t*)(sb + OFF_AL + ro);
                al[mi][1] = *(const uint32_t*)(sb + OFF_AL + ro + 8 * ROWB);
                al[mi][2] = *(const uint32_t*)(sb + OFF_AL + ro + 16);
                al[mi][3] = *(const uint32_t*)(sb + OFF_AL + ro + 8 * ROWB + 16);
            }
#pragma unroll
            for (int ni = 0; ni < 4; ni++) {
                uint32_t ro = (uint32_t)((wn * 32 + ni * 8 + (lane >> 2)) * ROWB
                                         + ksb + (lane & 3) * 4);
                bh[ni][0] = *(const uint32_t*)(sb + OFF_BH + ro);
                bh[ni][1] = *(const uint32_t*)(sb + OFF_BH + ro + 16);
                bl[ni][0] = *(const uint32_t*)(sb + OFF_BL + ro);
                bl[ni][1] = *(const uint32_t*)(sb + OFF_BL + ro + 16);
            }
#pragma unroll
            for (int mi = 0; mi < 4; mi++)
#pragma unroll
                for (int ni = 0; ni < 4; ni++) {
                    mma_bf16(acc[mi][ni], ah[mi], bh[ni]);
                    mma_bf16(acc[mi][ni], al[mi], bh[ni]);
                    mma_bf16(acc[mi][ni], ah[mi], bl[ni]);
                }
        }
    };

    stage(0, 0);
    cp_commit();
    for (int ck = 0; ck < nk; ck++) {
        if (ck + 1 < nk) {
            stage(ck + 1, (ck + 1) & 1);
            cp_commit();
            cp_wait<1>();
        } else {
            cp_wait<0>();
        }
        __syncthreads();
        compute(ck & 1);
        __syncthreads();
    }

    // epilogue: fragment -> global
#pragma unroll
    for (int mi = 0; mi < 4; mi++)
#pragma unroll
        for (int ni = 0; ni < 4; ni++) {
            int row = m0 + wm * 64 + mi * 16 + (lane >> 2);
            int col = n0 + wn * 32 + ni * 8 + (lane & 3) * 2;
            float2 v0 = {acc[mi][ni][0], acc[mi][ni][1]};
            float2 v1 = {acc[mi][ni][2], acc[mi][ni][3]};
            *(float2*)(C + (size_t)row * N + col)       = v0;
            *(float2*)(C + (size_t)(row + 8) * N + col) = v1;
        }
}

// ---------------------------------------------------------------------------
// RoPE, in place (unchanged from passing version).
// ---------------------------------------------------------------------------
__global__ void rope_kernel(float* __restrict__ t, const float* __restrict__ cs,
                            const float* __restrict__ sn, int heads, int total_pairs)
{
    int i = blockIdx.x * blockDim.x + threadIdx.x;
    if (i >= total_pairs) return;
    int j = i & (HALFD - 1);
    int s = (i / (HALFD * heads)) % SS;
    float2 v = *(float2*)(t + 2 * (size_t)i);
    float c  = cs[s * HALFD + j];
    float sv = sn[s * HALFD + j];
    float2 r;
    r.x = v.x * c - v.y * sv;
    r.y = v.x * sv + v.y * c;
    *(float2*)(t + 2 * (size_t)i) = r;
}

// ---------------------------------------------------------------------------
// Causal flash attention (unchanged from passing version).
// ---------------------------------------------------------------------------
__global__ __launch_bounds__(256) void attn_kernel(
    const float* __restrict__ Q, const float* __restrict__ Kg,
    const float* __restrict__ Vg, float* __restrict__ O)
{
    __shared__ float Ks[64][68];
    __shared__ float Vs[64][68];

    const int tid  = threadIdx.x;
    const int m0   = blockIdx.x * 64;
    const int bh   = blockIdx.y;
    const int b    = bh >> 5;
    const int h    = bh & 31;
    const int kvh  = h >> 2;
    const int r    = tid >> 2;
    const int q4   = tid & 3;
    const int qpos = m0 + r;

    float q[64];
    {
        const float* qp = Q + (((size_t)(b * SS + qpos)) * NH + h) * HDIM;
#pragma unroll
        for (int d4 = 0; d4 < 16; d4++) {
            float4 v = *(const float4*)(qp + d4 * 4);
            q[4 * d4 + 0] = v.x * 0.125f;
            q[4 * d4 + 1] = v.y * 0.125f;
            q[4 * d4 + 2] = v.z * 0.125f;
            q[4 * d4 + 3] = v.w * 0.125f;
        }
    }

    float oa[16];
#pragma unroll
    for (int i = 0; i < 16; i++) oa[i] = 0.f;
    float mrow = -1e30f, lrow = 0.f;

    const int ntiles = blockIdx.x + 1;
    for (int jt = 0; jt < ntiles; jt++) {
        const int n0 = jt * 64;
        __syncthreads();
#pragma unroll
        for (int i = 0; i < 4; i++) {
            int f  = tid + i * 256;
            int rr = f >> 4;
            int c4 = (f & 15) << 2;
            size_t src = (((size_t)(b * SS + n0 + rr)) * NKV + kvh) * HDIM + c4;
            *(float4*)&Ks[rr][c4] = *(const float4*)(Kg + src);
            *(float4*)&Vs[rr][c4] = *(const float4*)(Vg + src);
        }
        __syncthreads();

        float svv[16];
#pragma unroll
        for (int cc = 0; cc < 16; cc++) {
            int c = q4 * 16 + cc;
            const float4* kr = (const float4*)&Ks[c][0];
            float a0 = 0.f, a1 = 0.f, a2 = 0.f, a3 = 0.f;
#pragma unroll
            for (int d4 = 0; d4 < 16; d4++) {
                float4 kv = kr[d4];
                a0 += q[4 * d4 + 0] * kv.x;
                a1 += q[4 * d4 + 1] * kv.y;
                a2 += q[4 * d4 + 2] * kv.z;
                a3 += q[4 * d4 + 3] * kv.w;
            }
            float val = (a0 + a1) + (a2 + a3);
            svv[cc] = (n0 + c <= qpos) ? val : -1e30f;
        }

        float tmax = svv[0];
#pragma unroll
        for (int cc = 1; cc < 16; cc++) tmax = fmaxf(tmax, svv[cc]);
        tmax = fmaxf(tmax, __shfl_xor_sync(0xffffffffu, tmax, 1));
        tmax = fmaxf(tmax, __shfl_xor_sync(0xffffffffu, tmax, 2));
        float mnew  = fmaxf(mrow, tmax);
        float alpha = __expf(mrow - mnew);
        float ps = 0.f;
#pragma unroll
        for (int cc = 0; cc < 16; cc++) {
            float p = __expf(svv[cc] - mnew);
            svv[cc] = p;
            ps += p;
        }
        ps += __shfl_xor_sync(0xffffffffu, ps, 1);
        ps += __shfl_xor_sync(0xffffffffu, ps, 2);
        lrow = lrow * alpha + ps;
        mrow = mnew;
#pragma unroll
        for (int i = 0; i < 16; i++) oa[i] *= alpha;

        __syncthreads();
#pragma unroll
        for (int cc4 = 0; cc4 < 4; cc4++)
            *(float4*)&Ks[r][q4 * 16 + cc4 * 4] =
                make_float4(svv[cc4 * 4 + 0], svv[cc4 * 4 + 1],
                            svv[cc4 * 4 + 2], svv[cc4 * 4 + 3]);
        __syncthreads();

#pragma unroll
        for (int c4 = 0; c4 < 16; c4++) {
            float4 p4 = *(const float4*)&Ks[r][c4 * 4];
            float pv[4] = {p4.x, p4.y, p4.z, p4.w};
#pragma unroll
            for (int u = 0; u < 4; u++) {
                const float4* vr = (const float4*)&Vs[c4 * 4 + u][q4 * 16];
#pragma unroll
                for (int w = 0; w < 4; w++) {
                    float4 vv = vr[w];
                    oa[w * 4 + 0] += pv[u] * vv.x;
                    oa[w * 4 + 1] += pv[u] * vv.y;
                    oa[w * 4 + 2] += pv[u] * vv.z;
                    oa[w * 4 + 3] += pv[u] * vv.w;
                }
            }
        }
    }

    float inv = 1.0f / lrow;
    float* op = O + (((size_t)(b * SS + qpos)) * NH + h) * HDIM + q4 * 16;
#pragma unroll
    for (int w = 0; w < 4; w++) {
        float4 v = make_float4(oa[w * 4 + 0] * inv, oa[w * 4 + 1] * inv,
                               oa[w * 4 + 2] * inv, oa[w * 4 + 3] * inv);
        *(float4*)(op + w * 4) = v;
    }
}

// ---------------------------------------------------------------------------
extern "C" void kernel_launch(void* const* d_in, const int* in_sizes, int n_in,
                              void* d_out, int out_size)
{
    const float* x    = (const float*)d_in[0];
    const float* pcos = (const float*)d_in[1];
    const float* psin = (const float*)d_in[2];
    const float* wq   = (const float*)d_in[3];
    const float* wk   = (const float*)d_in[4];
    const float* wv   = (const float*)d_in[5];
    const float* wo   = (const float*)d_in[6];
    float* out        = (float*)d_out;

    float *Qd, *Kd, *Vd, *AOd;
    cudaGetSymbolAddress((void**)&Qd,  g_Q);
    cudaGetSymbolAddress((void**)&Kd,  g_K);
    cudaGetSymbolAddress((void**)&Vd,  g_V);
    cudaGetSymbolAddress((void**)&AOd, g_AO);
    __nv_bfloat16 *xh, *xl, *aoh, *aol, *wqh, *wql, *wkh, *wkl, *wvh, *wvl, *woh, *wol;
    cudaGetSymbolAddress((void**)&xh,  g_xh);  cudaGetSymbolAddress((void**)&xl,  g_xl);
    cudaGetSymbolAddress((void**)&aoh, g_aoh); cudaGetSymbolAddress((void**)&aol, g_aol);
    cudaGetSymbolAddress((void**)&wqh, g_wqh); cudaGetSymbolAddress((void**)&wql, g_wql);
    cudaGetSymbolAddress((void**)&wkh, g_wkh); cudaGetSymbolAddress((void**)&wkl, g_wkl);
    cudaGetSymbolAddress((void**)&wvh, g_wvh); cudaGetSymbolAddress((void**)&wvl, g_wvl);
    cudaGetSymbolAddress((void**)&woh, g_woh); cudaGetSymbolAddress((void**)&wol, g_wol);

    cudaFuncSetAttribute(gemm_mma_kernel,
                         cudaFuncAttributeMaxDynamicSharedMemorySize, GEMM_SMEM);

    const int M = BB * SS;                   // 4096

    // split activations, transpose+split weights
    int xn4 = (M * DD) / 4;
    split_kernel<<<(xn4 + 255) / 256, 256>>>(x, xh, xl, xn4);
    dim3 tb(32, 8);
    tsplit_kernel<<<dim3(DD / 32,  DD / 32), tb>>>(wq, wqh, wql, DD, DD);
    tsplit_kernel<<<dim3(KVD / 32, DD / 32), tb>>>(wk, wkh, wkl, DD, KVD);
    tsplit_kernel<<<dim3(KVD / 32, DD / 32), tb>>>(wv, wvh, wvl, DD, KVD);
    tsplit_kernel<<<dim3(DD / 32,  DD / 32), tb>>>(wo, woh, wol, DD, DD);

    // QKV projections on tensor cores (mma.sync HMMA path)
    dim3 gq(DD / 128, M / 128);              // (16, 32)
    dim3 gkv(KVD / 128, M / 128);            // (4, 32)
    gemm_mma_kernel<<<gq,  256, GEMM_SMEM>>>(xh, xl, wqh, wql, Qd, M, DD,  DD);
    gemm_mma_kernel<<<gkv, 256, GEMM_SMEM>>>(xh, xl, wkh, wkl, Kd, M, KVD, DD);
    gemm_mma_kernel<<<gkv, 256, GEMM_SMEM>>>(xh, xl, wvh, wvl, Vd, M, KVD, DD);

    // RoPE
    int qpairs = BB * SS * NH * HALFD;
    int kpairs = BB * SS * NKV * HALFD;
    rope_kernel<<<(qpairs + 255) / 256, 256>>>(Qd, pcos, psin, NH, qpairs);
    rope_kernel<<<(kpairs + 255) / 256, 256>>>(Kd, pcos, psin, NKV, kpairs);

    // causal flash attention
    dim3 ga(SS / 64, BB * NH);
    attn_kernel<<<ga, 256>>>(Qd, Kd, Vd, AOd);

    // output projection
    int an4 = (M * DD) / 4;
    split_kernel<<<(an4 + 255) / 256, 256>>>(AOd, aoh, aol, an4);
    gemm_mma_kernel<<<gq, 256, GEMM_SMEM>>>(aoh, aol, woh, wol, out, M, DD, DD);
}

// round 12
// speedup vs baseline: 1.2858x; 1.0226x over previous
#include <cuda_runtime.h>
#include <cuda_bf16.h>
#include <math.h>
#include <stdint.h>

#define BB   4
#define SS   1024
#define DD   2048
#define NH   32
#define NKV  8
#define HDIM 64
#define HALFD 32
#define KVD  (NKV * HDIM)   // 512

// ---------------- scratch (__device__ globals; no allocs allowed) ----------
__device__ float g_Q [BB * SS * NH  * HDIM];
__device__ float g_K [BB * SS * NKV * HDIM];
__device__ float g_V [BB * SS * NKV * HDIM];
__device__ float g_AO[BB * SS * DD];

__device__ __nv_bfloat16 g_xh [BB * SS * DD];
__device__ __nv_bfloat16 g_xl [BB * SS * DD];
__device__ __nv_bfloat16 g_aoh[BB * SS * DD];
__device__ __nv_bfloat16 g_aol[BB * SS * DD];
// transposed weights [N,K] row-major, split hi/lo
__device__ __nv_bfloat16 g_wqh[DD  * DD];
__device__ __nv_bfloat16 g_wql[DD  * DD];
__device__ __nv_bfloat16 g_wkh[KVD * DD];
__device__ __nv_bfloat16 g_wkl[KVD * DD];
__device__ __nv_bfloat16 g_wvh[KVD * DD];
__device__ __nv_bfloat16 g_wvl[KVD * DD];
__device__ __nv_bfloat16 g_woh[DD  * DD];
__device__ __nv_bfloat16 g_wol[DD  * DD];

// ---------------- helpers (baseline PTX only: sm_80-level features) --------
static __device__ __forceinline__ uint32_t smem_u32(const void* p) {
    uint32_t a;
    asm("{ .reg .u64 t; cvta.to.shared.u64 t, %1; cvt.u32.u64 %0, t; }"
        : "=r"(a) : "l"(p));
    return a;
}
static __device__ __forceinline__ void cp_async16(uint32_t saddr, const void* g) {
    asm volatile("cp.async.cg.shared.global [%0], [%1], 16;"
                 :: "r"(saddr), "l"(g) : "memory");
}
static __device__ __forceinline__ void cp_commit() {
    asm volatile("cp.async.commit_group;" ::: "memory");
}
template <int N>
static __device__ __forceinline__ void cp_wait() {
    asm volatile("cp.async.wait_group %0;" :: "n"(N) : "memory");
}
// ldmatrix x4: four 8x8 b16 tiles; lanes 0-7/8-15/16-23/24-31 give row addrs
static __device__ __forceinline__ void ldm_x4(uint32_t* d, uint32_t addr) {
    asm volatile("ldmatrix.sync.aligned.m8n8.x4.shared.b16 {%0,%1,%2,%3}, [%4];"
                 : "=r"(d[0]), "=r"(d[1]), "=r"(d[2]), "=r"(d[3]) : "r"(addr));
}
// D = A(16x16 bf16, row) * B(16x8 bf16, col) + D, fp32 accumulate
static __device__ __forceinline__ void mma_bf16(float* c, const uint32_t* a,
                                                const uint32_t* b) {
    asm volatile(
        "mma.sync.aligned.m16n8k16.row.col.f32.bf16.bf16.f32 "
        "{%0,%1,%2,%3}, {%4,%5,%6,%7}, {%8,%9}, {%0,%1,%2,%3};"
        : "+f"(c[0]), "+f"(c[1]), "+f"(c[2]), "+f"(c[3])
        : "r"(a[0]), "r"(a[1]), "r"(a[2]), "r"(a[3]), "r"(b[0]), "r"(b[1]));
}

// ---------------------------------------------------------------------------
// split: h = bf16(x), l = bf16(x - h).  n % 4 == 0.
// ---------------------------------------------------------------------------
__global__ void split_kernel(const float* __restrict__ x,
                             __nv_bfloat16* __restrict__ h,
                             __nv_bfloat16* __restrict__ l, int n4)
{
    int i = blockIdx.x * blockDim.x + threadIdx.x;
    if (i >= n4) return;
    float4 v = *((const float4*)x + i);
    __nv_bfloat16 h0 = __float2bfloat16(v.x), h1 = __float2bfloat16(v.y);
    __nv_bfloat16 h2 = __float2bfloat16(v.z), h3 = __float2bfloat16(v.w);
    __nv_bfloat162 hh0 = {h0, h1}, hh1 = {h2, h3};
    __nv_bfloat162 ll0 = {__float2bfloat16(v.x - __bfloat162float(h0)),
                          __float2bfloat16(v.y - __bfloat162float(h1))};
    __nv_bfloat162 ll1 = {__float2bfloat16(v.z - __bfloat162float(h2)),
                          __float2bfloat16(v.w - __bfloat162float(h3))};
    ((__nv_bfloat162*)h)[2 * i]     = hh0;
    ((__nv_bfloat162*)h)[2 * i + 1] = hh1;
    ((__nv_bfloat162*)l)[2 * i]     = ll0;
    ((__nv_bfloat162*)l)[2 * i + 1] = ll1;
}

// ---------------------------------------------------------------------------
// transpose + split: W[K,N] fp32 -> Th/Tl[N,K] bf16.  K,N % 32 == 0.
// ---------------------------------------------------------------------------
__global__ void tsplit_kernel(const float* __restrict__ W,
                              __nv_bfloat16* __restrict__ Th,
                              __nv_bfloat16* __restrict__ Tl, int K, int N)
{
    __shared__ float t[32][33];
    int n0 = blockIdx.x * 32, k0 = blockIdx.y * 32;
    int tx = threadIdx.x, ty = threadIdx.y;
#pragma unroll
    for (int i = 0; i < 4; i++)
        t[ty + i * 8][tx] = W[(size_t)(k0 + ty + i * 8) * N + n0 + tx];
    __syncthreads();
#pragma unroll
    for (int i = 0; i < 4; i++) {
        float v = t[tx][ty + i * 8];
        __nv_bfloat16 h = __float2bfloat16(v);
        size_t o = (size_t)(n0 + ty + i * 8) * K + k0 + tx;
        Th[o] = h;
        Tl[o] = __float2bfloat16(v - __bfloat162float(h));
    }
}

// ---------------------------------------------------------------------------
// mma.sync split-bf16 GEMM: C[M,N] = Ahl[M,K] x Bhl[N,K]^T  (fp32)
// 512 thr (16 warps, 4x4), CTA tile 128x128, warp tile 32x32, BK=32.
// ldmatrix.x4 fragment loads (conflict-free via 80B row stride).
// cp.async double buffer. dynamic smem = 2 x 40960 = 81920 B.
// ---------------------------------------------------------------------------
#define GSTRIDE  40                       // bf16 per smem row (32 data + 8 pad)
#define ROWB     (GSTRIDE * 2)            // 80 bytes
#define TILE_B   (128 * ROWB)             // 10240
#define OFF_AH   0
#define OFF_AL   TILE_B
#define OFF_BH   (2 * TILE_B)
#define OFF_BL   (3 * TILE_B)
#define BUF_B    (4 * TILE_B)             // 40960
#define GEMM_SMEM (2 * BUF_B)             // 81920

__global__ __launch_bounds__(512, 1) void gemm_mma_kernel(
    const __nv_bfloat16* __restrict__ Ah, const __nv_bfloat16* __restrict__ Al,
    const __nv_bfloat16* __restrict__ Bh, const __nv_bfloat16* __restrict__ Bl,
    float* __restrict__ C, int M, int N, int K)
{
    extern __shared__ char smem[];
    const int tid  = threadIdx.x;
    const int wid  = tid >> 5;
    const int lane = tid & 31;
    const int m0   = blockIdx.y * 128;
    const int n0   = blockIdx.x * 128;
    const int wm   = wid & 3;             // warp row (0..3) -> 32 rows
    const int wn   = wid >> 2;            // warp col (0..3) -> 32 cols
    const uint32_t sbase = smem_u32(smem);

    // ldmatrix per-lane address components (within a warp tile / k-chunk)
    const int a_r = lane & 15;                      // A: row 0..15 of 16-row tile
    const int a_c = (lane & 16) ? 16 : 0;           // A: +16B for k8..15 tiles
    const int b_r = (lane & 7) + ((lane & 16) ? 8 : 0);  // B: n-row 0..15
    const int b_c = (lane & 8) ? 16 : 0;            // B: +16B for k8..15 tiles

    float acc[2][4][4];
#pragma unroll
    for (int a = 0; a < 2; a++)
#pragma unroll
        for (int b = 0; b < 4; b++)
#pragma unroll
            for (int c = 0; c < 4; c++) acc[a][b][c] = 0.f;

    const int nk = K >> 5;                // chunks of 32

    // stage chunk ck into buffer buf (1 x 16B slot per tile per thread)
    auto stage = [&](int ck, int buf) {
        const int k0 = ck << 5;
        const uint32_t sb = sbase + buf * BUF_B;
        int row = tid >> 2;               // 0..127
        int seg = tid & 3;                // 16B segment within 64B of K-data
        uint32_t so = (uint32_t)(row * ROWB + seg * 16);
        size_t ga = (size_t)(m0 + row) * K + k0 + seg * 8;
        size_t gb = (size_t)(n0 + row) * K + k0 + seg * 8;
        cp_async16(sb + OFF_AH + so, Ah + ga);
        cp_async16(sb + OFF_AL + so, Al + ga);
        cp_async16(sb + OFF_BH + so, Bh + gb);
        cp_async16(sb + OFF_BL + so, Bl + gb);
    };

    auto compute = [&](int buf) {
        const uint32_t sb = sbase + buf * BUF_B;
        const uint32_t aBaseH = sb + OFF_AH + (uint32_t)((wm * 32 + a_r) * ROWB) + a_c;
        const uint32_t aBaseL = sb + OFF_AL + (uint32_t)((wm * 32 + a_r) * ROWB) + a_c;
        const uint32_t bBaseH = sb + OFF_BH + (uint32_t)((wn * 32 + b_r) * ROWB) + b_c;
        const uint32_t bBaseL = sb + OFF_BL + (uint32_t)((wn * 32 + b_r) * ROWB) + b_c;
#pragma unroll
        for (int ks = 0; ks < 2; ks++) {  // two k16 steps in BK=32
            const uint32_t ksb = ks * 32; // byte offset of k-step (16 bf16)
            uint32_t ah[2][4], al[2][4], bh[4][2], bl[4][2];
#pragma unroll
            for (int mi = 0; mi < 2; mi++) {
                ldm_x4(ah[mi], aBaseH + (uint32_t)(mi * 16 * ROWB) + ksb);
                ldm_x4(al[mi], aBaseL + (uint32_t)(mi * 16 * ROWB) + ksb);
            }
#pragma unroll
            for (int np = 0; np < 2; np++) {       // ni pairs (0,1) and (2,3)
                uint32_t th[4], tl[4];
                ldm_x4(th, bBaseH + (uint32_t)(np * 16 * ROWB) + ksb);
                ldm_x4(tl, bBaseL + (uint32_t)(np * 16 * ROWB) + ksb);
                bh[np * 2][0] = th[0];     bh[np * 2][1] = th[1];
                bh[np * 2 + 1][0] = th[2]; bh[np * 2 + 1][1] = th[3];
                bl[np * 2][0] = tl[0];     bl[np * 2][1] = tl[1];
                bl[np * 2 + 1][0] = tl[2]; bl[np * 2 + 1][1] = tl[3];
            }
#pragma unroll
            for (int mi = 0; mi < 2; mi++)
#pragma unroll
                for (int ni = 0; ni < 4; ni++) {
                    mma_bf16(acc[mi][ni], ah[mi], bh[ni]);
                    mma_bf16(acc[mi][ni], al[mi], bh[ni]);
                    mma_bf16(acc[mi][ni], ah[mi], bl[ni]);
                }
        }
    };

    stage(0, 0);
    cp_commit();
    for (int ck = 0; ck < nk; ck++) {
        if (ck + 1 < nk) {
            stage(ck + 1, (ck + 1) & 1);
            cp_commit();
            cp_wait<1>();
        } else {
            cp_wait<0>();
        }
        __syncthreads();
        compute(ck & 1);
        __syncthreads();
    }

    // epilogue: fragment -> global
#pragma unroll
    for (int mi = 0; mi < 2; mi++)
#pragma unroll
        for (int ni = 0; ni < 4; ni++) {
            int row = m0 + wm * 32 + mi * 16 + (lane >> 2);
            int col = n0 + wn * 32 + ni * 8 + (lane & 3) * 2;
            float2 v0 = {acc[mi][ni][0], acc[mi][ni][1]};
            float2 v1 = {acc[mi][ni][2], acc[mi][ni][3]};
            *(float2*)(C + (size_t)row * N + col)       = v0;
            *(float2*)(C + (size_t)(row + 8) * N + col) = v1;
        }
}

// ---------------------------------------------------------------------------
// RoPE, in place (unchanged from passing version).
// ---------------------------------------------------------------------------
__global__ void rope_kernel(float* __restrict__ t, const float* __restrict__ cs,
                            const float* __restrict__ sn, int heads, int total_pairs)
{
    int i = blockIdx.x * blockDim.x + threadIdx.x;
    if (i >= total_pairs) return;
    int j = i & (HALFD - 1);
    int s = (i / (HALFD * heads)) % SS;
    float2 v = *(float2*)(t + 2 * (size_t)i);
    float c  = cs[s * HALFD + j];
    float sv = sn[s * HALFD + j];
    float2 r;
    r.x = v.x * c - v.y * sv;
    r.y = v.x * sv + v.y * c;
    *(float2*)(t + 2 * (size_t)i) = r;
}

// ---------------------------------------------------------------------------
// Causal flash attention (unchanged from passing version).
// ---------------------------------------------------------------------------
__global__ __launch_bounds__(256) void attn_kernel(
    const float* __restrict__ Q, const float* __restrict__ Kg,
    const float* __restrict__ Vg, float* __restrict__ O)
{
    __shared__ float Ks[64][68];
    __shared__ float Vs[64][68];

    const int tid  = threadIdx.x;
    const int m0   = blockIdx.x * 64;
    const int bh   = blockIdx.y;
    const int b    = bh >> 5;
    const int h    = bh & 31;
    const int kvh  = h >> 2;
    const int r    = tid >> 2;
    const int q4   = tid & 3;
    const int qpos = m0 + r;

    float q[64];
    {
        const float* qp = Q + (((size_t)(b * SS + qpos)) * NH + h) * HDIM;
#pragma unroll
        for (int d4 = 0; d4 < 16; d4++) {
            float4 v = *(const float4*)(qp + d4 * 4);
            q[4 * d4 + 0] = v.x * 0.125f;
            q[4 * d4 + 1] = v.y * 0.125f;
            q[4 * d4 + 2] = v.z * 0.125f;
            q[4 * d4 + 3] = v.w * 0.125f;
        }
    }

    float oa[16];
#pragma unroll
    for (int i = 0; i < 16; i++) oa[i] = 0.f;
    float mrow = -1e30f, lrow = 0.f;

    const int ntiles = blockIdx.x + 1;
    for (int jt = 0; jt < ntiles; jt++) {
        const int n0 = jt * 64;
        __syncthreads();
#pragma unroll
        for (int i = 0; i < 4; i++) {
            int f  = tid + i * 256;
            int rr = f >> 4;
            int c4 = (f & 15) << 2;
            size_t src = (((size_t)(b * SS + n0 + rr)) * NKV + kvh) * HDIM + c4;
            *(float4*)&Ks[rr][c4] = *(const float4*)(Kg + src);
            *(float4*)&Vs[rr][c4] = *(const float4*)(Vg + src);
        }
        __syncthreads();

        float svv[16];
#pragma unroll
        for (int cc = 0; cc < 16; cc++) {
            int c = q4 * 16 + cc;
            const float4* kr = (const float4*)&Ks[c][0];
            float a0 = 0.f, a1 = 0.f, a2 = 0.f, a3 = 0.f;
#pragma unroll
            for (int d4 = 0; d4 < 16; d4++) {
                float4 kv = kr[d4];
                a0 += q[4 * d4 + 0] * kv.x;
                a1 += q[4 * d4 + 1] * kv.y;
                a2 += q[4 * d4 + 2] * kv.z;
                a3 += q[4 * d4 + 3] * kv.w;
            }
            float val = (a0 + a1) + (a2 + a3);
            svv[cc] = (n0 + c <= qpos) ? val : -1e30f;
        }

        float tmax = svv[0];
#pragma unroll
        for (int cc = 1; cc < 16; cc++) tmax = fmaxf(tmax, svv[cc]);
        tmax = fmaxf(tmax, __shfl_xor_sync(0xffffffffu, tmax, 1));
        tmax = fmaxf(tmax, __shfl_xor_sync(0xffffffffu, tmax, 2));
        float mnew  = fmaxf(mrow, tmax);
        float alpha = __expf(mrow - mnew);
        float ps = 0.f;
#pragma unroll
        for (int cc = 0; cc < 16; cc++) {
            float p = __expf(svv[cc] - mnew);
            svv[cc] = p;
            ps += p;
        }
        ps += __shfl_xor_sync(0xffffffffu, ps, 1);
        ps += __shfl_xor_sync(0xffffffffu, ps, 2);
        lrow = lrow * alpha + ps;
        mrow = mnew;
#pragma unroll
        for (int i = 0; i < 16; i++) oa[i] *= alpha;

        __syncthreads();
#pragma unroll
        for (int cc4 = 0; cc4 < 4; cc4++)
            *(float4*)&Ks[r][q4 * 16 + cc4 * 4] =
                make_float4(svv[cc4 * 4 + 0], svv[cc4 * 4 + 1],
                            svv[cc4 * 4 + 2], svv[cc4 * 4 + 3]);
        __syncthreads();

#pragma unroll
        for (int c4 = 0; c4 < 16; c4++) {
            float4 p4 = *(const float4*)&Ks[r][c4 * 4];
            float pv[4] = {p4.x, p4.y, p4.z, p4.w};
#pragma unroll
            for (int u = 0; u < 4; u++) {
                const float4* vr = (const float4*)&Vs[c4 * 4 + u][q4 * 16];
#pragma unroll
                for (int w = 0; w < 4; w++) {
                    float4 vv = vr[w];
                    oa[w * 4 + 0] += pv[u] * vv.x;
                    oa[w * 4 + 1] += pv[u] * vv.y;
                    oa[w * 4 + 2] += pv[u] * vv.z;
                    oa[w * 4 + 3] += pv[u] * vv.w;
                }
            }
        }
    }

    float inv = 1.0f / lrow;
    float* op = O + (((size_t)(b * SS + qpos)) * NH + h) * HDIM + q4 * 16;
#pragma unroll
    for (int w = 0; w < 4; w++) {
        float4 v = make_float4(oa[w * 4 + 0] * inv, oa[w * 4 + 1] * inv,
                               oa[w * 4 + 2] * inv, oa[w * 4 + 3] * inv);
        *(float4*)(op + w * 4) = v;
    }
}

// ---------------------------------------------------------------------------
extern "C" void kernel_launch(void* const* d_in, const int* in_sizes, int n_in,
                              void* d_out, int out_size)
{
    const float* x    = (const float*)d_in[0];
    const float* pcos = (const float*)d_in[1];
    const float* psin = (const float*)d_in[2];
    const float* wq   = (const float*)d_in[3];
    const float* wk   = (const float*)d_in[4];
    const float* wv   = (const float*)d_in[5];
    const float* wo   = (const float*)d_in[6];
    float* out        = (float*)d_out;

    float *Qd, *Kd, *Vd, *AOd;
    cudaGetSymbolAddress((void**)&Qd,  g_Q);
    cudaGetSymbolAddress((void**)&Kd,  g_K);
    cudaGetSymbolAddress((void**)&Vd,  g_V);
    cudaGetSymbolAddress((void**)&AOd, g_AO);
    __nv_bfloat16 *xh, *xl, *aoh, *aol, *wqh, *wql, *wkh, *wkl, *wvh, *wvl, *woh, *wol;
    cudaGetSymbolAddress((void**)&xh,  g_xh);  cudaGetSymbolAddress((void**)&xl,  g_xl);
    cudaGetSymbolAddress((void**)&aoh, g_aoh); cudaGetSymbolAddress((void**)&aol, g_aol);
    cudaGetSymbolAddress((void**)&wqh, g_wqh); cudaGetSymbolAddress((void**)&wql, g_wql);
    cudaGetSymbolAddress((void**)&wkh, g_wkh); cudaGetSymbolAddress((void**)&wkl, g_wkl);
    cudaGetSymbolAddress((void**)&wvh, g_wvh); cudaGetSymbolAddress((void**)&wvl, g_wvl);
    cudaGetSymbolAddress((void**)&woh, g_woh); cudaGetSymbolAddress((void**)&wol, g_wol);

    cudaFuncSetAttribute(gemm_mma_kernel,
                         cudaFuncAttributeMaxDynamicSharedMemorySize, GEMM_SMEM);

    const int M = BB * SS;                   // 4096

    // split activations, transpose+split weights
    int xn4 = (M * DD) / 4;
    split_kernel<<<(xn4 + 255) / 256, 256>>>(x, xh, xl, xn4);
    dim3 tb(32, 8);
    tsplit_kernel<<<dim3(DD / 32,  DD / 32), tb>>>(wq, wqh, wql, DD, DD);
    tsplit_kernel<<<dim3(KVD / 32, DD / 32), tb>>>(wk, wkh, wkl, DD, KVD);
    tsplit_kernel<<<dim3(KVD / 32, DD / 32), tb>>>(wv, wvh, wvl, DD, KVD);
    tsplit_kernel<<<dim3(DD / 32,  DD / 32), tb>>>(wo, woh, wol, DD, DD);

    // QKV projections on tensor cores (mma.sync HMMA path, ldmatrix feeds)
    dim3 gq(DD / 128, M / 128);              // (16, 32)
    dim3 gkv(KVD / 128, M / 128);            // (4, 32)
    gemm_mma_kernel<<<gq,  512, GEMM_SMEM>>>(xh, xl, wqh, wql, Qd, M, DD,  DD);
    gemm_mma_kernel<<<gkv, 512, GEMM_SMEM>>>(xh, xl, wkh, wkl, Kd, M, KVD, DD);
    gemm_mma_kernel<<<gkv, 512, GEMM_SMEM>>>(xh, xl, wvh, wvl, Vd, M, KVD, DD);

    // RoPE
    int qpairs = BB * SS * NH * HALFD;
    int kpairs = BB * SS * NKV * HALFD;
    rope_kernel<<<(qpairs + 255) / 256, 256>>>(Qd, pcos, psin, NH, qpairs);
    rope_kernel<<<(kpairs + 255) / 256, 256>>>(Kd, pcos, psin, NKV, kpairs);

    // causal flash attention
    dim3 ga(SS / 64, BB * NH);
    attn_kernel<<<ga, 256>>>(Qd, Kd, Vd, AOd);

    // output projection
    int an4 = (M * DD) / 4;
    split_kernel<<<(an4 + 255) / 256, 256>>>(AOd, aoh, aol, an4);
    gemm_mma_kernel<<<gq, 512, GEMM_SMEM>>>(aoh, aol, woh, wol, out, M, DD, DD);
}